// round 15
// baseline (speedup 1.0000x reference)
#include <cuda_runtime.h>
#include <cuda_fp16.h>
#include <math.h>
#include <stdint.h>

#define BATCH   2
#define SEQ     2048
#define DMODEL  2048
#define NHEADS  16
#define DHEAD   128
#define MTOT    (BATCH * SEQ)   // 4096

// ---------------------------------------------------------------------------
// Scratch buffers (allocation-free rule: __device__ globals) — fp16 dataflow
// ---------------------------------------------------------------------------
__device__ __half g_xh [(size_t)MTOT * DMODEL];
__device__ __half g_wqh[(size_t)DMODEL * DMODEL];
__device__ __half g_wkh[(size_t)DMODEL * DMODEL];
__device__ __half g_wvh[(size_t)DMODEL * DMODEL];
__device__ __half g_woh[(size_t)DMODEL * DMODEL];
__device__ __half g_qh [(size_t)MTOT * DMODEL];
__device__ __half g_kh [(size_t)MTOT * DMODEL];
__device__ __half g_vh [(size_t)MTOT * DMODEL];
__device__ __half g_aoh[(size_t)MTOT * DMODEL];

// ---------------------------------------------------------------------------
// Helpers (baseline-family PTX only: ldmatrix sm_75+, mma/cp.async sm_80+)
// ---------------------------------------------------------------------------
__device__ __forceinline__ uint32_t smem_u32(const void* p) {
    uint32_t a;
    asm("{ .reg .u64 t; cvta.to.shared.u64 t, %1; cvt.u32.u64 %0, t; }"
        : "=r"(a) : "l"(p));
    return a;
}

__device__ __forceinline__ void ldsm_x4(uint32_t addr, uint32_t& r0, uint32_t& r1,
                                        uint32_t& r2, uint32_t& r3) {
    asm volatile("ldmatrix.sync.aligned.m8n8.x4.shared.b16 {%0,%1,%2,%3}, [%4];"
                 : "=r"(r0), "=r"(r1), "=r"(r2), "=r"(r3) : "r"(addr));
}

__device__ __forceinline__ void ldsm_x4_t(uint32_t addr, uint32_t& r0, uint32_t& r1,
                                          uint32_t& r2, uint32_t& r3) {
    asm volatile("ldmatrix.sync.aligned.m8n8.x4.trans.shared.b16 {%0,%1,%2,%3}, [%4];"
                 : "=r"(r0), "=r"(r1), "=r"(r2), "=r"(r3) : "r"(addr));
}

__device__ __forceinline__ void mma16816(float* d, const uint32_t* a,
                                         uint32_t b0, uint32_t b1) {
    asm volatile("mma.sync.aligned.m16n8k16.row.col.f32.f16.f16.f32 "
                 "{%0,%1,%2,%3}, {%4,%5,%6,%7}, {%8,%9}, {%0,%1,%2,%3};"
                 : "+f"(d[0]), "+f"(d[1]), "+f"(d[2]), "+f"(d[3])
                 : "r"(a[0]), "r"(a[1]), "r"(a[2]), "r"(a[3]), "r"(b0), "r"(b1));
}

__device__ __forceinline__ float fast_exp2(float x) {
    float y;
    asm("ex2.approx.ftz.f32 %0, %1;" : "=f"(y) : "f"(x));
    return y;
}

#define CP_ASYNC16(smem, gptr) \
    asm volatile("cp.async.cg.shared.global [%0], [%1], 16;" \
                 :: "r"(smem), "l"(gptr) : "memory")
#define CP_COMMIT()  asm volatile("cp.async.commit_group;" ::: "memory")
#define CP_WAIT(n)   asm volatile("cp.async.wait_group %0;" :: "n"(n) : "memory")

// ---------------------------------------------------------------------------
// Fused fp32 -> fp16 converter: one launch handles x + all 4 weights.
// ---------------------------------------------------------------------------
__global__ __launch_bounds__(256)
void cvt_all(const float* __restrict__ x,  const float* __restrict__ wq,
             const float* __restrict__ wk, const float* __restrict__ wv,
             const float* __restrict__ wo,
             __half* __restrict__ xh,  __half* __restrict__ wqh,
             __half* __restrict__ wkh, __half* __restrict__ wvh,
             __half* __restrict__ woh)
{
    const float* src;
    __half* dst;
    int n;
    switch (blockIdx.y) {
        case 0:  src = x;  dst = xh;  n = MTOT * DMODEL;   break;
        case 1:  src = wq; dst = wqh; n = DMODEL * DMODEL; break;
        case 2:  src = wk; dst = wkh; n = DMODEL * DMODEL; break;
        case 3:  src = wv; dst = wvh; n = DMODEL * DMODEL; break;
        default: src = wo; dst = woh; n = DMODEL * DMODEL; break;
    }
    const int i = (blockIdx.x * 256 + threadIdx.x) * 8;
    if (i >= n) return;
    float4 v0 = *(const float4*)(src + i);
    float4 v1 = *(const float4*)(src + i + 4);
    __half2 h0 = __floats2half2_rn(v0.x, v0.y);
    __half2 h1 = __floats2half2_rn(v0.z, v0.w);
    __half2 h2 = __floats2half2_rn(v1.x, v1.y);
    __half2 h3 = __floats2half2_rn(v1.z, v1.w);
    *(uint4*)(dst + i) = make_uint4(*(uint32_t*)&h0, *(uint32_t*)&h1,
                                    *(uint32_t*)&h2, *(uint32_t*)&h3);
}

// ---------------------------------------------------------------------------
// HMMA fp16 GEMM core:  C[m][n] = sum_k A[m][k] * W[n][k]   (K-major NT)
// 128x128 CTA tile, 8 warps (4x2 -> warp tile 32x64), BK=64 (4 k-steps),
// cp.async 3-stage pipeline (36 KB/stage). Runtime rope; HOUT template.
// ---------------------------------------------------------------------------
#define BK       64
#define NCH      (DMODEL / BK)    // 32
#define LDS_ROW  72               // halves per smem row (64 + 8 pad)
#define STG_T_B  (128 * LDS_ROW * 2)  // bytes per tensor per stage = 18432
#define STG_B    (2 * STG_T_B)        // 36864 (A + W)
#define NSTAGE   3
#define GEMM_SMEM (NSTAGE * STG_B)    // 110592 bytes

template<bool HOUT>
__device__ __forceinline__
void gemm_body(const __half* __restrict__ A, const __half* __restrict__ W,
               void* __restrict__ Cv, bool rope, int m0, int n0)
{
    extern __shared__ char dsm[];
    const uint32_t sb = smem_u32(dsm);

    const int tid = threadIdx.x;
    const int wid = tid >> 5;
    const int lid = tid & 31;
    const int wm  = wid >> 1;
    const int wn  = wid & 1;

    // per-thread cp.async slice: row r (0..127), 32 halves at side*32 (4x16B)
    const int r    = tid >> 1;
    const int side = tid & 1;
    const __half* Ap = A + (size_t)(m0 + r) * DMODEL + side * 32;
    const __half* Wp = W + (size_t)(n0 + r) * DMODEL + side * 32;
    const uint32_t dA = sb + (uint32_t)(r * (LDS_ROW * 2) + side * 64);
    const uint32_t dW = dA + STG_T_B;

    auto issue = [&](int c) {
        const uint32_t so = (uint32_t)((c % NSTAGE) * STG_B);
        const __half* ga = Ap + c * BK;
        const __half* gw = Wp + c * BK;
        CP_ASYNC16(dA + so,      ga);
        CP_ASYNC16(dA + so + 16, ga + 8);
        CP_ASYNC16(dA + so + 32, ga + 16);
        CP_ASYNC16(dA + so + 48, ga + 24);
        CP_ASYNC16(dW + so,      gw);
        CP_ASYNC16(dW + so + 16, gw + 8);
        CP_ASYNC16(dW + so + 32, gw + 16);
        CP_ASYNC16(dW + so + 48, gw + 24);
        CP_COMMIT();
    };

    uint32_t offA[2], offB[4];
#pragma unroll
    for (int mt = 0; mt < 2; mt++) {
        const int row = wm * 32 + mt * 16 + (lid & 15);
        const int col = (lid >> 4) << 3;
        offA[mt] = (uint32_t)((row * LDS_ROW + col) * 2);
    }
#pragma unroll
    for (int nb = 0; nb < 4; nb++) {
        const int row = wn * 64 + nb * 16 + (lid & 7) + ((lid & 16) ? 8 : 0);
        const int col = (lid & 8) ? 8 : 0;
        offB[nb] = (uint32_t)((row * LDS_ROW + col) * 2 + STG_T_B);
    }

    float acc[2][8][4];
#pragma unroll
    for (int mt = 0; mt < 2; mt++)
#pragma unroll
        for (int nt = 0; nt < 8; nt++)
#pragma unroll
            for (int i = 0; i < 4; i++) acc[mt][nt][i] = 0.f;

    issue(0); issue(1);

    for (int c = 0; c < NCH; c++) {
        if (c == NCH - 1) { CP_WAIT(0); }    // drain everything for last chunk
        else              { CP_WAIT(1); }    // group c complete
        __syncthreads();                     // writes visible; stage (c-1) free
        if (c + 2 < NCH) issue(c + 2);

        const uint32_t st = sb + (uint32_t)((c % NSTAGE) * STG_B);
#pragma unroll
        for (int ks = 0; ks < 4; ks++) {
            const uint32_t kso = (uint32_t)(ks * 32);   // 16 halves per k-step
            uint32_t a[2][4], b[4][4];
#pragma unroll
            for (int mt = 0; mt < 2; mt++)
                ldsm_x4(st + offA[mt] + kso, a[mt][0], a[mt][1], a[mt][2], a[mt][3]);
#pragma unroll
            for (int nb = 0; nb < 4; nb++)
                ldsm_x4(st + offB[nb] + kso, b[nb][0], b[nb][1], b[nb][2], b[nb][3]);
#pragma unroll
            for (int mt = 0; mt < 2; mt++)
#pragma unroll
                for (int nb = 0; nb < 4; nb++) {
                    mma16816(acc[mt][2 * nb],     a[mt], b[nb][0], b[nb][1]);
                    mma16816(acc[mt][2 * nb + 1], a[mt], b[nb][2], b[nb][3]);
                }
        }
    }

    // ---- epilogue (+RoPE); even/odd col pair lives inside one thread ----
    const int qr = lid >> 2;
    const int qc = (lid & 3) * 2;

    float inv[8];
    if (rope) {
#pragma unroll
        for (int nt = 0; nt < 8; nt++) {
            const int d = wn * 64 + nt * 8 + qc;
            inv[nt] = powf(10000.f, -(float)d * (1.f / 128.f));
        }
    }

#pragma unroll
    for (int mt = 0; mt < 2; mt++) {
#pragma unroll
        for (int h = 0; h < 2; h++) {
            const int m = m0 + wm * 32 + mt * 16 + qr + h * 8;
            const float pos = (float)(m & (SEQ - 1));
#pragma unroll
            for (int nt = 0; nt < 8; nt++) {
                float e = acc[mt][nt][2 * h + 0];
                float o = acc[mt][nt][2 * h + 1];
                if (rope) {
                    float sn, cs;
                    sincosf(pos * inv[nt], &sn, &cs);
                    const float e2 = e * cs - o * sn;
                    o = e * sn + o * cs;
                    e = e2;
                }
                const int col = n0 + wn * 64 + nt * 8 + qc;
                if (HOUT) {
                    __half2 hv = __floats2half2_rn(e, o);
                    *reinterpret_cast<__half2*>(
                        (__half*)Cv + (size_t)m * DMODEL + col) = hv;
                } else {
                    *(float2*)((float*)Cv + (size_t)m * DMODEL + col) =
                        make_float2(e, o);
                }
            }
        }
    }
}

// Fused QKV: blockIdx.z selects weight/output; RoPE for Q (z=0) and K (z=1).
__global__ __launch_bounds__(256, 2)
void gemm_qkv(const __half* __restrict__ A,
              const __half* __restrict__ W0, const __half* __restrict__ W1,
              const __half* __restrict__ W2,
              __half* __restrict__ C0, __half* __restrict__ C1,
              __half* __restrict__ C2)
{
    const int z = blockIdx.z;
    const __half* W = (z == 0) ? W0 : (z == 1) ? W1 : W2;
    __half*       C = (z == 0) ? C0 : (z == 1) ? C1 : C2;
    gemm_body<true>(A, W, C, z < 2, blockIdx.y * 128, blockIdx.x * 128);
}

// Output projection: fp16 in, fp32 out, no RoPE.
__global__ __launch_bounds__(256, 2)
void gemm_out(const __half* __restrict__ A, const __half* __restrict__ W,
              float* __restrict__ C)
{
    gemm_body<false>(A, W, C, false, blockIdx.y * 128, blockIdx.x * 128);
}

// ---------------------------------------------------------------------------
// HMMA flash attention (causal). Grid (SEQ/128, NHEADS, BATCH), 256 threads.
// 8 warps x 16 query rows; KV tiles of 64, double-buffered via cp.async.
// S-frag -> P A-frag register identity (no P through smem). fp32 softmax.
// ---------------------------------------------------------------------------
#define AT_STRIDE  136                      // halves per row (128 + 8)
#define AT_ROW_B   (AT_STRIDE * 2)          // 272 bytes
#define AT_STAGE_B (128 * AT_ROW_B)         // 34816 bytes (K rows 0-63, V 64-127)
#define ATTN_SMEM  (2 * AT_STAGE_B)         // 69632 bytes

__global__ __launch_bounds__(256)
void attn_hmma(const __half* __restrict__ Q, const __half* __restrict__ K,
               const __half* __restrict__ V, __half* __restrict__ O)
{
    extern __shared__ char dsm[];
    __half* sKV = (__half*)dsm;
    const uint32_t sb = smem_u32(dsm);

    const int tid = threadIdx.x;
    const int wid = tid >> 5;
    const int lid = tid & 31;
    const int qt  = blockIdx.x;
    const int h   = blockIdx.y;
    const int b   = blockIdx.z;
    const int q0  = qt * 128;

    const size_t base = (size_t)b * SEQ * DMODEL + (size_t)h * DHEAD;
    const float K1 = 0.08838834764831845f * 1.4426950408889634f;  // scale*log2(e)

    // ---- stage Q tile (128x128 half) in stage 0, pull A-frags ----
    for (int i = tid; i < 128 * 16; i += 256) {
        const int rr = i >> 4;
        const int db = i & 15;
        *(uint4*)&sKV[rr * AT_STRIDE + db * 8] =
            *(const uint4*)&Q[base + (size_t)(q0 + rr) * DMODEL + db * 8];
    }
    __syncthreads();

    uint32_t qf[8][4];
    {
        const int arow = wid * 16 + (lid & 15);
        const int acol = (lid >> 4) << 3;
#pragma unroll
        for (int kst = 0; kst < 8; kst++)
            ldsm_x4(sb + (uint32_t)((arow * AT_STRIDE + kst * 16 + acol) * 2),
                    qf[kst][0], qf[kst][1], qf[kst][2], qf[kst][3]);
    }
    __syncthreads();   // all Q frags read before stage 0 is overwritten by KV

    auto issueKV = [&](int kt, int s) {
        const uint32_t stg = sb + (uint32_t)(s * AT_STAGE_B);
        const int kv0 = kt * 64;
#pragma unroll
        for (int j = 0; j < 4; j++) {
            const int idx = tid + j * 256;    // 0..1023
            const int c   = idx >> 4;         // kv row 0..63
            const int db  = idx & 15;         // 16B chunk
            const size_t src = base + (size_t)(kv0 + c) * DMODEL + db * 8;
            CP_ASYNC16(stg + (uint32_t)(c * AT_ROW_B + db * 16),        &K[src]);
            CP_ASYNC16(stg + (uint32_t)((64 + c) * AT_ROW_B + db * 16), &V[src]);
        }
        CP_COMMIT();
    };

    float acc[16][4];
#pragma unroll
    for (int nt = 0; nt < 16; nt++)
#pragma unroll
        for (int i = 0; i < 4; i++) acc[nt][i] = 0.f;
    float mrow0 = -1e30f, mrow1 = -1e30f, lrow0 = 0.f, lrow1 = 0.f;

    const int r0  = lid >> 2;
    const int qcl = (lid & 3) * 2;
    const int wrow_min = q0 + wid * 16;
    const int ntiles = 2 * qt + 2;

    issueKV(0, 0);

    for (int kt = 0; kt < ntiles; kt++) {
        const int s   = kt & 1;
        const int kv0 = kt * 64;

        if (kt + 1 < ntiles) { issueKV(kt + 1, s ^ 1); CP_WAIT(1); }
        else                 { CP_WAIT(0); }
        __syncthreads();

        if (kv0 <= wrow_min + 15) {
            const uint32_t stg = sb + (uint32_t)(s * AT_STAGE_B);

            // ---- S = Q K^T (16x64 per warp) ----
            float sc[8][4];
#pragma unroll
            for (int nt = 0; nt < 8; nt++)
#pragma unroll
                for (int i = 0; i < 4; i++) sc[nt][i] = 0.f;

#pragma unroll
            for (int kst = 0; kst < 8; kst++) {
#pragma unroll
                for (int np = 0; np < 4; np++) {
                    uint32_t b0, b1, b2, b3;
                    const int krow = np * 16 + (lid & 7) + ((lid & 16) ? 8 : 0);
                    const int kcol = kst * 16 + ((lid & 8) ? 8 : 0);
                    ldsm_x4(stg + (uint32_t)((krow * AT_STRIDE + kcol) * 2),
                            b0, b1, b2, b3);
                    mma16816(sc[2 * np],     qf[kst], b0, b1);
                    mma16816(sc[2 * np + 1], qf[kst], b2, b3);
                }
            }

            // ---- causal mask (only near-diagonal warp-tiles) ----
            const int row0 = wrow_min + r0;
            const int row1 = row0 + 8;
            if (kv0 + 63 > wrow_min) {
#pragma unroll
                for (int nt = 0; nt < 8; nt++) {
                    const int col = kv0 + nt * 8 + qcl;
                    if (col     > row0) sc[nt][0] = -1e30f;
                    if (col + 1 > row0) sc[nt][1] = -1e30f;
                    if (col     > row1) sc[nt][2] = -1e30f;
                    if (col + 1 > row1) sc[nt][3] = -1e30f;
                }
            }

            // ---- online softmax (quad reduce over lanes sharing a row) ----
            float m0 = -1e30f, m1 = -1e30f;
#pragma unroll
            for (int nt = 0; nt < 8; nt++) {
                m0 = fmaxf(m0, fmaxf(sc[nt][0], sc[nt][1]));
                m1 = fmaxf(m1, fmaxf(sc[nt][2], sc[nt][3]));
            }
            m0 = fmaxf(m0, __shfl_xor_sync(0xffffffffu, m0, 1));
            m0 = fmaxf(m0, __shfl_xor_sync(0xffffffffu, m0, 2));
            m1 = fmaxf(m1, __shfl_xor_sync(0xffffffffu, m1, 1));
            m1 = fmaxf(m1, __shfl_xor_sync(0xffffffffu, m1, 2));

            const float mn0 = fmaxf(mrow0, m0);
            const float mn1 = fmaxf(mrow1, m1);
            const float al0 = fast_exp2((mrow0 - mn0) * K1);
            const float al1 = fast_exp2((mrow1 - mn1) * K1);
            mrow0 = mn0; mrow1 = mn1;
            const float nk0 = mn0 * K1;
            const float nk1 = mn1 * K1;

            float rs0 = 0.f, rs1 = 0.f;
            uint32_t ph[8][2];
#pragma unroll
            for (int nt = 0; nt < 8; nt++) {
                const float p0 = fast_exp2(fmaf(sc[nt][0], K1, -nk0));
                const float p1 = fast_exp2(fmaf(sc[nt][1], K1, -nk0));
                const float p2 = fast_exp2(fmaf(sc[nt][2], K1, -nk1));
                const float p3 = fast_exp2(fmaf(sc[nt][3], K1, -nk1));
                rs0 += p0 + p1;
                rs1 += p2 + p3;
                __half2 h0 = __floats2half2_rn(p0, p1);
                __half2 h1 = __floats2half2_rn(p2, p3);
                ph[nt][0] = *reinterpret_cast<uint32_t*>(&h0);
                ph[nt][1] = *reinterpret_cast<uint32_t*>(&h1);
            }
            rs0 += __shfl_xor_sync(0xffffffffu, rs0, 1);
            rs0 += __shfl_xor_sync(0xffffffffu, rs0, 2);
            rs1 += __shfl_xor_sync(0xffffffffu, rs1, 1);
            rs1 += __shfl_xor_sync(0xffffffffu, rs1, 2);
            lrow0 = lrow0 * al0 + rs0;
            lrow1 = lrow1 * al1 + rs1;

#pragma unroll
            for (int nt = 0; nt < 16; nt++) {
                acc[nt][0] *= al0; acc[nt][1] *= al0;
                acc[nt][2] *= al1; acc[nt][3] *= al1;
            }

            // ---- O += P V (P A-frags straight from S fragments) ----
#pragma unroll
            for (int kc = 0; kc < 4; kc++) {
                uint32_t a[4] = { ph[2 * kc][0], ph[2 * kc][1],
                                  ph[2 * kc + 1][0], ph[2 * kc + 1][1] };
#pragma unroll
                for (int dp = 0; dp < 8; dp++) {
                    uint32_t v0, v1, v2, v3;
                    const int vrow = 64 + kc * 16 + (lid & 7) + ((lid & 8) ? 8 : 0);
                    const int vcol = dp * 16 + ((lid & 16) ? 8 : 0);
                    ldsm_x4_t(stg + (uint32_t)((vrow * AT_STRIDE + vcol) * 2),
                              v0, v1, v2, v3);
                    mma16816(acc[2 * dp],     a, v0, v1);
                    mma16816(acc[2 * dp + 1], a, v2, v3);
                }
            }
        }
        __syncthreads();   // all warps done with stage s before it is rewritten
    }

    // ---- normalize + fp16 store ----
    const float inv0 = 1.f / lrow0;
    const float inv1 = 1.f / lrow1;
    const int gr0 = q0 + wid * 16 + r0;
    __half* o0 = O + base + (size_t)gr0 * DMODEL;
    __half* o1 = O + base + (size_t)(gr0 + 8) * DMODEL;
#pragma unroll
    for (int nt = 0; nt < 16; nt++) {
        const int col = nt * 8 + qcl;
        __half2 h0 = __floats2half2_rn(acc[nt][0] * inv0, acc[nt][1] * inv0);
        __half2 h1 = __floats2half2_rn(acc[nt][2] * inv1, acc[nt][3] * inv1);
        *reinterpret_cast<__half2*>(o0 + col) = h0;
        *reinterpret_cast<__half2*>(o1 + col) = h1;
    }
}

// ---------------------------------------------------------------------------
// Launch
// ---------------------------------------------------------------------------
extern "C" void kernel_launch(void* const* d_in, const int* in_sizes, int n_in,
                              void* d_out, int out_size)
{
    const float* x  = (const float*)d_in[0];
    const float* wq = (const float*)d_in[1];
    const float* wk = (const float*)d_in[2];
    const float* wv = (const float*)d_in[3];
    const float* wo = (const float*)d_in[4];
    float* out = (float*)d_out;

    __half *xh, *wqh, *wkh, *wvh, *woh, *qh, *kh, *vh, *aoh;
    cudaGetSymbolAddress((void**)&xh,  g_xh);
    cudaGetSymbolAddress((void**)&wqh, g_wqh);
    cudaGetSymbolAddress((void**)&wkh, g_wkh);
    cudaGetSymbolAddress((void**)&wvh, g_wvh);
    cudaGetSymbolAddress((void**)&woh, g_woh);
    cudaGetSymbolAddress((void**)&qh,  g_qh);
    cudaGetSymbolAddress((void**)&kh,  g_kh);
    cudaGetSymbolAddress((void**)&vh,  g_vh);
    cudaGetSymbolAddress((void**)&aoh, g_aoh);

    cudaFuncSetAttribute(gemm_qkv,
                         cudaFuncAttributeMaxDynamicSharedMemorySize, GEMM_SMEM);
    cudaFuncSetAttribute(gemm_out,
                         cudaFuncAttributeMaxDynamicSharedMemorySize, GEMM_SMEM);
    cudaFuncSetAttribute(attn_hmma,
                         cudaFuncAttributeMaxDynamicSharedMemorySize, ATTN_SMEM);

    // ---- one fused fp32 -> fp16 conversion launch (x + 4 weights) ----
    cvt_all<<<dim3(MTOT * DMODEL / 2048, 5), 256>>>(
        x, wq, wk, wv, wo, xh, wqh, wkh, wvh, woh);

    // ---- fused Q/K/V projections (z selects operand; RoPE on z<2) ----
    gemm_qkv<<<dim3(DMODEL / 128, MTOT / 128, 3), 256, GEMM_SMEM>>>(
        xh, wqh, wkh, wvh, qh, kh, vh);

    attn_hmma<<<dim3(SEQ / 128, NHEADS, BATCH), 256, ATTN_SMEM>>>(qh, kh, vh, aoh);

    gemm_out<<<dim3(DMODEL / 128, MTOT / 128), 256, GEMM_SMEM>>>(aoh, woh, out);
}